// round 1
// baseline (speedup 1.0000x reference)
#include <cuda_runtime.h>

#define DIMM 1024
#define HEADS 16
#define DHEAD 64
#define SEQ 2048
#define BATCH 2
#define ROWS (BATCH * SEQ)      // 4096
#define QKV_N (3 * DIMM)        // 3072
#define SCALE 0.03125f          // 1024^-0.5

// Scratch (static device arrays: allocation-free per harness rules)
__device__ float g_qkv[(size_t)ROWS * QKV_N];   // [4096, 3072] : Q|K|V
__device__ float g_att[(size_t)ROWS * DIMM];    // [4096, 1024] attention output

// ---------------------------------------------------------------------------
// SGEMM: C[M,N] = A[M,K] @ B[K,N] (+ bias). Row-major. M%128==0, N%128==0, K%8==0.
// 256 threads, BM=BN=128, BK=8, per-thread 8x8.
// ---------------------------------------------------------------------------
__global__ void __launch_bounds__(256, 2)
sgemm_kernel(const float* __restrict__ A, const float* __restrict__ B,
             const float* __restrict__ bias, float* __restrict__ C,
             int M, int N, int K)
{
    __shared__ float As[8][132];   // transposed: As[k][m]
    __shared__ float Bs[8][132];   // Bs[k][n]

    const int tid = threadIdx.x;
    const int tx = tid & 15;       // N direction
    const int ty = tid >> 4;       // M direction
    const int m0 = blockIdx.y * 128;
    const int n0 = blockIdx.x * 128;

    const float* Ab = A + (size_t)m0 * K;
    const float* Bb = B + n0;

    const int am = tid >> 1;            // 0..127
    const int ak = (tid & 1) * 4;       // 0 or 4
    const int bk = tid >> 5;            // 0..7
    const int bn = (tid & 31) * 4;      // 0..124

    float acc[8][8];
#pragma unroll
    for (int i = 0; i < 8; i++)
#pragma unroll
        for (int j = 0; j < 8; j++) acc[i][j] = 0.0f;

    for (int k0 = 0; k0 < K; k0 += 8) {
        float4 av = *(const float4*)(Ab + (size_t)am * K + k0 + ak);
        float4 bv = *(const float4*)(Bb + (size_t)(k0 + bk) * N + bn);
        __syncthreads();   // prev iter consumers done before overwrite
        As[ak + 0][am] = av.x;
        As[ak + 1][am] = av.y;
        As[ak + 2][am] = av.z;
        As[ak + 3][am] = av.w;
        *(float4*)&Bs[bk][bn] = bv;
        __syncthreads();

#pragma unroll
        for (int k = 0; k < 8; k++) {
            float a[8], b[8];
            *(float4*)(a)     = *(const float4*)&As[k][ty * 8];
            *(float4*)(a + 4) = *(const float4*)&As[k][ty * 8 + 4];
            *(float4*)(b)     = *(const float4*)&Bs[k][tx * 8];
            *(float4*)(b + 4) = *(const float4*)&Bs[k][tx * 8 + 4];
#pragma unroll
            for (int i = 0; i < 8; i++)
#pragma unroll
                for (int j = 0; j < 8; j++)
                    acc[i][j] += a[i] * b[j];
        }
    }

    float bia[8];
#pragma unroll
    for (int j = 0; j < 8; j++)
        bia[j] = bias ? bias[n0 + tx * 8 + j] : 0.0f;

#pragma unroll
    for (int i = 0; i < 8; i++) {
        int m = m0 + ty * 8 + i;
        float* crow = C + (size_t)m * N + n0 + tx * 8;
        float4 r0, r1;
        r0.x = acc[i][0] + bia[0]; r0.y = acc[i][1] + bia[1];
        r0.z = acc[i][2] + bia[2]; r0.w = acc[i][3] + bia[3];
        r1.x = acc[i][4] + bia[4]; r1.y = acc[i][5] + bia[5];
        r1.z = acc[i][6] + bia[6]; r1.w = acc[i][7] + bia[7];
        *(float4*)(crow)     = r0;
        *(float4*)(crow + 4) = r1;
    }
}

// ---------------------------------------------------------------------------
// Flash attention: one CTA handles one (batch, head, 64-row Q tile).
// 256 threads as 16x16; thread (tx,ty) owns S rows ty*4..+4, cols tx*4..+4.
// Online softmax, O accumulated in registers, P staged through smem for P@V.
// ---------------------------------------------------------------------------
__global__ void __launch_bounds__(256, 2)
attn_kernel(const float* __restrict__ qkv, float* __restrict__ out)
{
    extern __shared__ float sm[];
    float* Qs = sm;                 // [64][65]
    float* Ks = Qs + 64 * 65;       // [64][65]
    float* Vs = Ks + 64 * 65;       // [64][64]
    float* Ps = Vs + 64 * 64;       // [64][64]

    const int tid = threadIdx.x;
    const int tx = tid & 15;
    const int ty = tid >> 4;
    const int qt = blockIdx.x;      // q tile (0..31)
    const int h  = blockIdx.y;      // head
    const int b  = blockIdx.z;      // batch

    const float* qbase = qkv + (size_t)(b * SEQ) * QKV_N + h * DHEAD;

    // load Q tile: [64 rows][64 d], row-major with pad 65
    const int lr = tid >> 4;            // 0..15
    const int ld = (tid & 15) * 4;      // 0..60
#pragma unroll
    for (int p = 0; p < 4; p++) {
        int r = lr + p * 16;
        float4 v = *(const float4*)(qbase + (size_t)(qt * 64 + r) * QKV_N + ld);
        float* q = &Qs[r * 65 + ld];
        q[0] = v.x; q[1] = v.y; q[2] = v.z; q[3] = v.w;
    }

    float m_run[4], l_run[4], o[4][4];
#pragma unroll
    for (int i = 0; i < 4; i++) {
        m_run[i] = -1e30f;
        l_run[i] = 0.0f;
#pragma unroll
        for (int j = 0; j < 4; j++) o[i][j] = 0.0f;
    }

    for (int kt = 0; kt < SEQ / 64; kt++) {
        __syncthreads();   // prev P@V done before overwriting K/V
#pragma unroll
        for (int p = 0; p < 4; p++) {
            int r = lr + p * 16;
            const float* kp = qbase + DIMM + (size_t)(kt * 64 + r) * QKV_N + ld;
            float4 kv = *(const float4*)kp;
            float4 vv = *(const float4*)(kp + DIMM);
            float* ks = &Ks[r * 65 + ld];
            ks[0] = kv.x; ks[1] = kv.y; ks[2] = kv.z; ks[3] = kv.w;
            *(float4*)&Vs[r * 64 + ld] = vv;
        }
        __syncthreads();

        // S = Q @ K^T (this tile): s[i][j], rows ty*4+i, cols tx*4+j
        float s[4][4];
#pragma unroll
        for (int i = 0; i < 4; i++)
#pragma unroll
            for (int j = 0; j < 4; j++) s[i][j] = 0.0f;

#pragma unroll 16
        for (int k = 0; k < 64; k++) {
            float a[4], bb[4];
#pragma unroll
            for (int i = 0; i < 4; i++) a[i]  = Qs[(ty * 4 + i) * 65 + k];
#pragma unroll
            for (int j = 0; j < 4; j++) bb[j] = Ks[(tx * 4 + j) * 65 + k];
#pragma unroll
            for (int i = 0; i < 4; i++)
#pragma unroll
                for (int j = 0; j < 4; j++)
                    s[i][j] += a[i] * bb[j];
        }

        // online softmax update per row
#pragma unroll
        for (int i = 0; i < 4; i++) {
            float mx = -1e30f;
#pragma unroll
            for (int j = 0; j < 4; j++) {
                s[i][j] *= SCALE;
                mx = fmaxf(mx, s[i][j]);
            }
#pragma unroll
            for (int ofs = 8; ofs >= 1; ofs >>= 1)
                mx = fmaxf(mx, __shfl_xor_sync(0xffffffffu, mx, ofs, 16));

            float mnew = fmaxf(m_run[i], mx);
            float alpha = __expf(m_run[i] - mnew);
            float p[4], ps = 0.0f;
#pragma unroll
            for (int j = 0; j < 4; j++) {
                p[j] = __expf(s[i][j] - mnew);
                ps += p[j];
            }
#pragma unroll
            for (int ofs = 8; ofs >= 1; ofs >>= 1)
                ps += __shfl_xor_sync(0xffffffffu, ps, ofs, 16);

            l_run[i] = l_run[i] * alpha + ps;
            m_run[i] = mnew;
#pragma unroll
            for (int j = 0; j < 4; j++) {
                o[i][j] *= alpha;
                Ps[(ty * 4 + i) * 64 + tx * 4 + j] = p[j];
            }
        }
        __syncthreads();

        // O += P @ V  : o[i][c], c = tx*4..+4
#pragma unroll 8
        for (int j = 0; j < 64; j++) {
            float4 vv = *(const float4*)&Vs[j * 64 + tx * 4];
#pragma unroll
            for (int i = 0; i < 4; i++) {
                float pv = Ps[(ty * 4 + i) * 64 + j];
                o[i][0] += pv * vv.x;
                o[i][1] += pv * vv.y;
                o[i][2] += pv * vv.z;
                o[i][3] += pv * vv.w;
            }
        }
    }

    // write O / l  -> g_att [row][h*64 + c]
    float* ob = out + (size_t)(b * SEQ + qt * 64) * DIMM + h * DHEAD;
#pragma unroll
    for (int i = 0; i < 4; i++) {
        int r = ty * 4 + i;
        float inv = 1.0f / l_run[i];
        float4 res;
        res.x = o[i][0] * inv; res.y = o[i][1] * inv;
        res.z = o[i][2] * inv; res.w = o[i][3] * inv;
        *(float4*)(ob + (size_t)r * DIMM + tx * 4) = res;
    }
}

// ---------------------------------------------------------------------------

extern "C" void kernel_launch(void* const* d_in, const int* in_sizes, int n_in,
                              void* d_out, int out_size)
{
    const float* x     = (const float*)d_in[0];   // [2,2048,1024]
    const float* W_qkv = (const float*)d_in[1];   // [1024,3072]
    const float* W_out = (const float*)d_in[2];   // [1024,1024]
    const float* b_out = (const float*)d_in[3];   // [1024]
    float* out = (float*)d_out;                   // [2,2048,1024]

    float* qkv = nullptr;
    float* att = nullptr;
    cudaGetSymbolAddress((void**)&qkv, g_qkv);
    cudaGetSymbolAddress((void**)&att, g_att);

    // 1) QKV projection: [4096,1024] @ [1024,3072]
    {
        dim3 grid(QKV_N / 128, ROWS / 128);
        sgemm_kernel<<<grid, 256>>>(x, W_qkv, nullptr, qkv, ROWS, QKV_N, DIMM);
    }

    // 2) attention
    {
        int smem = (64 * 65 * 2 + 64 * 64 * 2) * (int)sizeof(float);  // 66048
        cudaFuncSetAttribute(attn_kernel,
                             cudaFuncAttributeMaxDynamicSharedMemorySize, smem);
        dim3 grid(SEQ / 64, HEADS, BATCH);
        attn_kernel<<<grid, 256, smem>>>(qkv, att);
    }

    // 3) output projection + bias: [4096,1024] @ [1024,1024] + b
    {
        dim3 grid(DIMM / 128, ROWS / 128);
        sgemm_kernel<<<grid, 256>>>(att, W_out, b_out, out, ROWS, DIMM, DIMM);
    }
}

// round 3
// speedup vs baseline: 2.9425x; 2.9425x over previous
#include <cuda_runtime.h>
#include <cstdint>

#define DIMM 1024
#define HEADS 16
#define DHEAD 64
#define SEQ 2048
#define BATCH 2
#define ROWS (BATCH * SEQ)      // 4096
#define QKV_N (3 * DIMM)        // 3072
#define SCALE 0.03125f          // 1024^-0.5

// Scratch (static device arrays: allocation-free per harness rules)
__device__ float g_qkv[(size_t)ROWS * QKV_N];   // [4096, 3072] : Q|K|V
__device__ float g_att[(size_t)ROWS * DIMM];    // [4096, 1024] attention output

// ---------------------------------------------------------------------------
// helpers
// ---------------------------------------------------------------------------
__device__ __forceinline__ uint32_t f2tf32(float x) {
    uint32_t r;
    asm("cvt.rna.tf32.f32 %0, %1;" : "=r"(r) : "f"(x));
    return r;
}

__device__ __forceinline__ void mma_tf32(float* d, const uint32_t* a,
                                         const uint32_t* b, const float* c) {
    asm volatile(
        "mma.sync.aligned.m16n8k8.row.col.f32.tf32.tf32.f32 "
        "{%0,%1,%2,%3}, {%4,%5,%6,%7}, {%8,%9}, {%10,%11,%12,%13};"
        : "=f"(d[0]), "=f"(d[1]), "=f"(d[2]), "=f"(d[3])
        : "r"(a[0]), "r"(a[1]), "r"(a[2]), "r"(a[3]),
          "r"(b[0]), "r"(b[1]),
          "f"(c[0]), "f"(c[1]), "f"(c[2]), "f"(c[3]));
}

// ---------------------------------------------------------------------------
// tf32 tensor-core GEMM: C[M,N] = A[M,K] @ B[K,N] (+bias).
// BM=128, BN=128, BK=16, 256 threads = 8 warps (4M x 2N), warp tile 32x64.
// Double-buffered smem. A stored [m][k] stride 20, B stored [k][n] stride 136.
// ---------------------------------------------------------------------------
#define SA 20    // As row stride (floats): 20 mod 32 -> conflict-free frag loads
#define SB 136   // Bs row stride: 136 mod 32 = 8 -> conflict-free frag loads

__global__ void __launch_bounds__(256, 2)
gemm_tf32_kernel(const float* __restrict__ A, const float* __restrict__ B,
                 const float* __restrict__ bias, float* __restrict__ C,
                 int M, int N, int K)
{
    __shared__ uint32_t As[2][128 * SA];
    __shared__ uint32_t Bs[2][16 * SB];

    const int tid  = threadIdx.x;
    const int lane = tid & 31;
    const int warp = tid >> 5;
    const int g = lane >> 2;        // group id (row within frag)
    const int t = lane & 3;         // thread-in-group (col within frag)

    const int m0 = blockIdx.y * 128;
    const int n0 = blockIdx.x * 128;
    const int wm = (warp >> 1) * 32;
    const int wn = (warp & 1) * 64;

    // global load mapping
    const int a_row = tid >> 2;            // 0..63 (+64)
    const int a_col = (tid & 3) * 4;
    const int b_row = tid >> 5;            // 0..7 (+8)
    const int b_col = (tid & 31) * 4;

    const float* Ab = A + (size_t)(m0 + a_row) * K + a_col;
    const float* Bb = B + (size_t)b_row * N + n0 + b_col;

    float acc[2][8][4];
#pragma unroll
    for (int i = 0; i < 2; i++)
#pragma unroll
        for (int j = 0; j < 8; j++)
#pragma unroll
            for (int c = 0; c < 4; c++) acc[i][j][c] = 0.0f;

    const int NIT = K / 16;

    float4 ra0, ra1, rb0, rb1;
    // prologue: load iter 0
    ra0 = *(const float4*)(Ab);
    ra1 = *(const float4*)(Ab + (size_t)64 * K);
    rb0 = *(const float4*)(Bb);
    rb1 = *(const float4*)(Bb + (size_t)8 * N);

    // store iter 0 into buf 0
    {
        uint4 u;
        u.x = f2tf32(ra0.x); u.y = f2tf32(ra0.y); u.z = f2tf32(ra0.z); u.w = f2tf32(ra0.w);
        *(uint4*)&As[0][a_row * SA + a_col] = u;
        u.x = f2tf32(ra1.x); u.y = f2tf32(ra1.y); u.z = f2tf32(ra1.z); u.w = f2tf32(ra1.w);
        *(uint4*)&As[0][(a_row + 64) * SA + a_col] = u;
        u.x = f2tf32(rb0.x); u.y = f2tf32(rb0.y); u.z = f2tf32(rb0.z); u.w = f2tf32(rb0.w);
        *(uint4*)&Bs[0][b_row * SB + b_col] = u;
        u.x = f2tf32(rb1.x); u.y = f2tf32(rb1.y); u.z = f2tf32(rb1.z); u.w = f2tf32(rb1.w);
        *(uint4*)&Bs[0][(b_row + 8) * SB + b_col] = u;
    }
    __syncthreads();

    for (int it = 0; it < NIT; it++) {
        const int cur = it & 1;
        if (it + 1 < NIT) {
            const float* Ap = Ab + (size_t)(it + 1) * 16;
            const float* Bp = Bb + (size_t)(it + 1) * 16 * N;
            ra0 = *(const float4*)(Ap);
            ra1 = *(const float4*)(Ap + (size_t)64 * K);
            rb0 = *(const float4*)(Bp);
            rb1 = *(const float4*)(Bp + (size_t)8 * N);
        }

        const uint32_t* as = As[cur];
        const uint32_t* bs = Bs[cur];
#pragma unroll
        for (int kk = 0; kk < 2; kk++) {
            uint32_t afr[2][4];
#pragma unroll
            for (int mt = 0; mt < 2; mt++) {
                int mr = wm + mt * 16 + g;
                afr[mt][0] = as[mr * SA + kk * 8 + t];
                afr[mt][1] = as[(mr + 8) * SA + kk * 8 + t];
                afr[mt][2] = as[mr * SA + kk * 8 + t + 4];
                afr[mt][3] = as[(mr + 8) * SA + kk * 8 + t + 4];
            }
            uint32_t bfr[8][2];
#pragma unroll
            for (int nt = 0; nt < 8; nt++) {
                int nc = wn + nt * 8 + g;
                bfr[nt][0] = bs[(kk * 8 + t) * SB + nc];
                bfr[nt][1] = bs[(kk * 8 + t + 4) * SB + nc];
            }
#pragma unroll
            for (int mt = 0; mt < 2; mt++)
#pragma unroll
                for (int nt = 0; nt < 8; nt++)
                    mma_tf32(acc[mt][nt], afr[mt], bfr[nt], acc[mt][nt]);
        }

        if (it + 1 < NIT) {
            const int nxt = 1 - cur;
            uint4 u;
            u.x = f2tf32(ra0.x); u.y = f2tf32(ra0.y); u.z = f2tf32(ra0.z); u.w = f2tf32(ra0.w);
            *(uint4*)&As[nxt][a_row * SA + a_col] = u;
            u.x = f2tf32(ra1.x); u.y = f2tf32(ra1.y); u.z = f2tf32(ra1.z); u.w = f2tf32(ra1.w);
            *(uint4*)&As[nxt][(a_row + 64) * SA + a_col] = u;
            u.x = f2tf32(rb0.x); u.y = f2tf32(rb0.y); u.z = f2tf32(rb0.z); u.w = f2tf32(rb0.w);
            *(uint4*)&Bs[nxt][b_row * SB + b_col] = u;
            u.x = f2tf32(rb1.x); u.y = f2tf32(rb1.y); u.z = f2tf32(rb1.z); u.w = f2tf32(rb1.w);
            *(uint4*)&Bs[nxt][(b_row + 8) * SB + b_col] = u;
            __syncthreads();
        }
    }

    // epilogue
#pragma unroll
    for (int mt = 0; mt < 2; mt++) {
#pragma unroll
        for (int nt = 0; nt < 8; nt++) {
            int row0 = m0 + wm + mt * 16 + g;
            int col  = n0 + wn + nt * 8 + 2 * t;
            float b0 = bias ? bias[col]     : 0.0f;
            float b1 = bias ? bias[col + 1] : 0.0f;
            float2 v0 = make_float2(acc[mt][nt][0] + b0, acc[mt][nt][1] + b1);
            float2 v1 = make_float2(acc[mt][nt][2] + b0, acc[mt][nt][3] + b1);
            *(float2*)(C + (size_t)row0 * N + col)       = v0;
            *(float2*)(C + (size_t)(row0 + 8) * N + col) = v1;
        }
    }
}

// ---------------------------------------------------------------------------
// Flash attention with tf32 mma. One CTA = (64-row Q tile, head, batch).
// 128 threads = 4 warps, each warp owns 16 Q rows. Q fragments in registers.
// ---------------------------------------------------------------------------
#define SK 68   // Ks stride: 68 mod 32 = 4
#define SV 72   // Vs stride: 72 mod 32 = 8
#define SP 68   // Ps/Qs stride

__global__ void __launch_bounds__(128)
attn_tf32_kernel(const float* __restrict__ qkv, float* __restrict__ out)
{
    extern __shared__ float sm[];
    float* Ks = sm;                  // [64][SK]
    float* Vs = Ks + 64 * SK;        // [64][SV]
    float* Ps = Vs + 64 * SV;        // [64][SP]  (also Qs at start)

    const int tid  = threadIdx.x;
    const int lane = tid & 31;
    const int warp = tid >> 5;
    const int g = lane >> 2;
    const int t = lane & 3;
    const int wm = warp * 16;

    const int qt = blockIdx.x;
    const int h  = blockIdx.y;
    const int b  = blockIdx.z;

    const float* base = qkv + (size_t)(b * SEQ) * QKV_N + h * DHEAD;

    // ---- load Q tile into Ps region, tf32-rounded ----
    const int lr  = tid >> 4;            // 0..7
    const int lc4 = (tid & 15) * 4;
#pragma unroll
    for (int p = 0; p < 8; p++) {
        int r = lr + p * 8;
        float4 v = *(const float4*)(base + (size_t)(qt * 64 + r) * QKV_N + lc4);
        float* q = &Ps[r * SP + lc4];
        q[0] = __uint_as_float(f2tf32(v.x));
        q[1] = __uint_as_float(f2tf32(v.y));
        q[2] = __uint_as_float(f2tf32(v.z));
        q[3] = __uint_as_float(f2tf32(v.w));
    }
    __syncthreads();

    // ---- build Q fragments (register-resident all kernel) ----
    uint32_t qf[8][4];
    {
        const uint32_t* qs = (const uint32_t*)Ps;
#pragma unroll
        for (int ks = 0; ks < 8; ks++) {
            qf[ks][0] = qs[(wm + g) * SP + ks * 8 + t];
            qf[ks][1] = qs[(wm + g + 8) * SP + ks * 8 + t];
            qf[ks][2] = qs[(wm + g) * SP + ks * 8 + t + 4];
            qf[ks][3] = qs[(wm + g + 8) * SP + ks * 8 + t + 4];
        }
    }

    float O[8][4];
#pragma unroll
    for (int d = 0; d < 8; d++)
#pragma unroll
        for (int c = 0; c < 4; c++) O[d][c] = 0.0f;
    float m0r = -1e30f, m1r = -1e30f, l0r = 0.0f, l1r = 0.0f;

    for (int kt = 0; kt < SEQ / 64; kt++) {
        __syncthreads();   // prior P@V reads of Ks/Vs done (also Qfrag build at kt=0)
        // ---- load K/V tile (tf32-rounded) ----
#pragma unroll
        for (int p = 0; p < 8; p++) {
            int r = lr + p * 8;
            const float* kp = base + DIMM + (size_t)(kt * 64 + r) * QKV_N + lc4;
            float4 kv = *(const float4*)kp;
            float4 vv = *(const float4*)(kp + DIMM);
            float4 ko, vo;
            ko.x = __uint_as_float(f2tf32(kv.x)); ko.y = __uint_as_float(f2tf32(kv.y));
            ko.z = __uint_as_float(f2tf32(kv.z)); ko.w = __uint_as_float(f2tf32(kv.w));
            vo.x = __uint_as_float(f2tf32(vv.x)); vo.y = __uint_as_float(f2tf32(vv.y));
            vo.z = __uint_as_float(f2tf32(vv.z)); vo.w = __uint_as_float(f2tf32(vv.w));
            *(float4*)&Ks[r * SK + lc4] = ko;
            *(float4*)&Vs[r * SV + lc4] = vo;
        }
        __syncthreads();

        // ---- S = Q @ K^T ----
        float S[8][4];
#pragma unroll
        for (int nt = 0; nt < 8; nt++)
#pragma unroll
            for (int c = 0; c < 4; c++) S[nt][c] = 0.0f;

        const uint32_t* ks32 = (const uint32_t*)Ks;
#pragma unroll
        for (int ks = 0; ks < 8; ks++) {
            uint32_t kb[8][2];
#pragma unroll
            for (int nt = 0; nt < 8; nt++) {
                kb[nt][0] = ks32[(nt * 8 + g) * SK + ks * 8 + t];
                kb[nt][1] = ks32[(nt * 8 + g) * SK + ks * 8 + t + 4];
            }
#pragma unroll
            for (int nt = 0; nt < 8; nt++)
                mma_tf32(S[nt], qf[ks], kb[nt], S[nt]);
        }

        // ---- online softmax (rows wm+g, wm+g+8; 4-lane groups share a row) ----
        float mx0 = -1e30f, mx1 = -1e30f;
#pragma unroll
        for (int nt = 0; nt < 8; nt++) {
            S[nt][0] *= SCALE; S[nt][1] *= SCALE;
            S[nt][2] *= SCALE; S[nt][3] *= SCALE;
            mx0 = fmaxf(mx0, fmaxf(S[nt][0], S[nt][1]));
            mx1 = fmaxf(mx1, fmaxf(S[nt][2], S[nt][3]));
        }
        mx0 = fmaxf(mx0, __shfl_xor_sync(0xffffffffu, mx0, 1));
        mx0 = fmaxf(mx0, __shfl_xor_sync(0xffffffffu, mx0, 2));
        mx1 = fmaxf(mx1, __shfl_xor_sync(0xffffffffu, mx1, 1));
        mx1 = fmaxf(mx1, __shfl_xor_sync(0xffffffffu, mx1, 2));

        float mn0 = fmaxf(m0r, mx0);
        float mn1 = fmaxf(m1r, mx1);
        float al0 = __expf(m0r - mn0);
        float al1 = __expf(m1r - mn1);
        m0r = mn0; m1r = mn1;

        float ps0 = 0.0f, ps1 = 0.0f;
#pragma unroll
        for (int nt = 0; nt < 8; nt++) {
            S[nt][0] = __expf(S[nt][0] - mn0);
            S[nt][1] = __expf(S[nt][1] - mn0);
            S[nt][2] = __expf(S[nt][2] - mn1);
            S[nt][3] = __expf(S[nt][3] - mn1);
            ps0 += S[nt][0] + S[nt][1];
            ps1 += S[nt][2] + S[nt][3];
        }
        ps0 += __shfl_xor_sync(0xffffffffu, ps0, 1);
        ps0 += __shfl_xor_sync(0xffffffffu, ps0, 2);
        ps1 += __shfl_xor_sync(0xffffffffu, ps1, 1);
        ps1 += __shfl_xor_sync(0xffffffffu, ps1, 2);
        l0r = l0r * al0 + ps0;
        l1r = l1r * al1 + ps1;

#pragma unroll
        for (int d = 0; d < 8; d++) {
            O[d][0] *= al0; O[d][1] *= al0;
            O[d][2] *= al1; O[d][3] *= al1;
        }

        // ---- store P (own warp rows only), tf32-rounded ----
#pragma unroll
        for (int nt = 0; nt < 8; nt++) {
            float2 p0 = make_float2(__uint_as_float(f2tf32(S[nt][0])),
                                    __uint_as_float(f2tf32(S[nt][1])));
            float2 p1 = make_float2(__uint_as_float(f2tf32(S[nt][2])),
                                    __uint_as_float(f2tf32(S[nt][3])));
            *(float2*)&Ps[(wm + g) * SP + nt * 8 + 2 * t]     = p0;
            *(float2*)&Ps[(wm + g + 8) * SP + nt * 8 + 2 * t] = p1;
        }
        __syncwarp();

        // ---- O += P @ V ----
        const uint32_t* ps32 = (const uint32_t*)Ps;
        const uint32_t* vs32 = (const uint32_t*)Vs;
#pragma unroll
        for (int j8 = 0; j8 < 8; j8++) {
            uint32_t pa[4];
            pa[0] = ps32[(wm + g) * SP + j8 * 8 + t];
            pa[1] = ps32[(wm + g + 8) * SP + j8 * 8 + t];
            pa[2] = ps32[(wm + g) * SP + j8 * 8 + t + 4];
            pa[3] = ps32[(wm + g + 8) * SP + j8 * 8 + t + 4];
            uint32_t vb[8][2];
#pragma unroll
            for (int dt = 0; dt < 8; dt++) {
                vb[dt][0] = vs32[(j8 * 8 + t) * SV + dt * 8 + g];
                vb[dt][1] = vs32[(j8 * 8 + t + 4) * SV + dt * 8 + g];
            }
#pragma unroll
            for (int dt = 0; dt < 8; dt++)
                mma_tf32(O[dt], pa, vb[dt], O[dt]);
        }
    }

    // ---- epilogue: normalize and write ----
    float inv0 = 1.0f / l0r;
    float inv1 = 1.0f / l1r;
    float* ob = out + (size_t)(b * SEQ + qt * 64) * DIMM + h * DHEAD;
#pragma unroll
    for (int dt = 0; dt < 8; dt++) {
        int col = dt * 8 + 2 * t;
        float2 v0 = make_float2(O[dt][0] * inv0, O[dt][1] * inv0);
        float2 v1 = make_float2(O[dt][2] * inv1, O[dt][3] * inv1);
        *(float2*)(ob + (size_t)(wm + g) * DIMM + col)     = v0;
        *(float2*)(ob + (size_t)(wm + g + 8) * DIMM + col) = v1;
    }
}

// ---------------------------------------------------------------------------

extern "C" void kernel_launch(void* const* d_in, const int* in_sizes, int n_in,
                              void* d_out, int out_size)
{
    const float* x     = (const float*)d_in[0];   // [2,2048,1024]
    const float* W_qkv = (const float*)d_in[1];   // [1024,3072]
    const float* W_out = (const float*)d_in[2];   // [1024,1024]
    const float* b_out = (const float*)d_in[3];   // [1024]
    float* out = (float*)d_out;                   // [2,2048,1024]

    float* qkv = nullptr;
    float* att = nullptr;
    cudaGetSymbolAddress((void**)&qkv, g_qkv);
    cudaGetSymbolAddress((void**)&att, g_att);

    // 1) QKV projection: [4096,1024] @ [1024,3072]
    {
        dim3 grid(QKV_N / 128, ROWS / 128);
        gemm_tf32_kernel<<<grid, 256>>>(x, W_qkv, nullptr, qkv, ROWS, QKV_N, DIMM);
    }

    // 2) attention
    {
        int smem = (64 * SK + 64 * SV + 64 * SP) * (int)sizeof(float);  // 53248
        cudaFuncSetAttribute(attn_tf32_kernel,
                             cudaFuncAttributeMaxDynamicSharedMemorySize, smem);
        dim3 grid(SEQ / 64, HEADS, BATCH);
        attn_tf32_kernel<<<grid, 128, smem>>>(qkv, att);
    }

    // 3) output projection + bias: [4096,1024] @ [1024,1024] + b
    {
        dim3 grid(DIMM / 128, ROWS / 128);
        gemm_tf32_kernel<<<grid, 256>>>(att, W_out, b_out, out, ROWS, DIMM, DIMM);
    }
}

// round 4
// speedup vs baseline: 5.6256x; 1.9119x over previous
#include <cuda_runtime.h>
#include <cuda_fp16.h>
#include <cstdint>

#define DIMM 1024
#define HEADS 16
#define DHEAD 64
#define SEQ 2048
#define BATCH 2
#define ROWS (BATCH * SEQ)      // 4096
#define QKV_N (3 * DIMM)        // 3072
#define SCALE 0.03125f          // 1024^-0.5

// fp16 scratch (static device arrays: allocation-free per harness rules)
__device__ __half g_qkv[(size_t)ROWS * QKV_N];   // [4096, 3072] : Q|K|V (half)
__device__ __half g_att[(size_t)ROWS * DIMM];    // [4096, 1024] attention out (half)

// ---------------------------------------------------------------------------
// helpers
// ---------------------------------------------------------------------------
__device__ __forceinline__ uint32_t sm_u32(const void* p) {
    return (uint32_t)__cvta_generic_to_shared(p);
}

// pack two floats to half2 (lo -> low 16 bits)
__device__ __forceinline__ uint32_t pack2(float lo, float hi) {
    uint32_t r;
    asm("cvt.rn.f16x2.f32 %0, %1, %2;" : "=r"(r) : "f"(hi), "f"(lo));
    return r;
}

__device__ __forceinline__ void ldsm4(uint32_t* r, uint32_t a) {
    asm volatile("ldmatrix.sync.aligned.m8n8.x4.shared.b16 {%0,%1,%2,%3}, [%4];"
                 : "=r"(r[0]), "=r"(r[1]), "=r"(r[2]), "=r"(r[3]) : "r"(a));
}
__device__ __forceinline__ void ldsm4t(uint32_t* r, uint32_t a) {
    asm volatile("ldmatrix.sync.aligned.m8n8.x4.trans.shared.b16 {%0,%1,%2,%3}, [%4];"
                 : "=r"(r[0]), "=r"(r[1]), "=r"(r[2]), "=r"(r[3]) : "r"(a));
}

__device__ __forceinline__ void mma16816(float* d, const uint32_t* a,
                                         const uint32_t* b, const float* c) {
    asm volatile(
        "mma.sync.aligned.m16n8k16.row.col.f32.f16.f16.f32 "
        "{%0,%1,%2,%3}, {%4,%5,%6,%7}, {%8,%9}, {%10,%11,%12,%13};"
        : "=f"(d[0]), "=f"(d[1]), "=f"(d[2]), "=f"(d[3])
        : "r"(a[0]), "r"(a[1]), "r"(a[2]), "r"(a[3]),
          "r"(b[0]), "r"(b[1]),
          "f"(c[0]), "f"(c[1]), "f"(c[2]), "f"(c[3]));
}

// ---------------------------------------------------------------------------
// GEMM 1: A f32 [M,K] @ B f32 [K,N] -> C half. BM=128 BN=128 BK=16.
// 256 thr = 8 warps (4m x 2n), warp tile 32x64, m16n8k16 HMMA, LDSM frags.
// ---------------------------------------------------------------------------
#define GSA 24    // As stride (halves): rows hit distinct 16B groups mod 128B
#define GSB 136   // Bs stride (halves)

__global__ void __launch_bounds__(256, 2)
gemm_f32a_kernel(const float* __restrict__ A, const float* __restrict__ B,
                 __half* __restrict__ C, int M, int N, int K)
{
    __shared__ __half As[2][128 * GSA];
    __shared__ __half Bs[2][16 * GSB];

    const int tid  = threadIdx.x;
    const int lane = tid & 31;
    const int warp = tid >> 5;
    const int g = lane >> 2;
    const int t = lane & 3;

    const int m0 = blockIdx.y * 128;
    const int n0 = blockIdx.x * 128;
    const int wm = (warp >> 1) * 32;
    const int wn = (warp & 1) * 64;

    const int a_row = tid >> 2;           // 0..63 (+64)
    const int a_col = (tid & 3) * 4;
    const int b_row = tid >> 5;           // 0..7 (+8)
    const int b_col = (tid & 31) * 4;

    const float* Ab = A + (size_t)(m0 + a_row) * K + a_col;
    const float* Bb = B + (size_t)b_row * N + n0 + b_col;

    // LDSM addresses
    const uint32_t as_base = sm_u32(&As[0][0]);
    const uint32_t bs_base = sm_u32(&Bs[0][0]);
    const uint32_t a_off = ((uint32_t)((lane & 15) * GSA + (lane >> 4) * 8)) * 2;
    const uint32_t b_off = ((uint32_t)((((lane >> 3) & 1) * 8 + (lane & 7)) * GSB
                                       + wn + (lane >> 4) * 8)) * 2;

    float acc[2][8][4];
#pragma unroll
    for (int i = 0; i < 2; i++)
#pragma unroll
        for (int j = 0; j < 8; j++)
#pragma unroll
            for (int c = 0; c < 4; c++) acc[i][j][c] = 0.0f;

    const int NIT = K >> 4;

    float4 ra0, ra1, rb0, rb1;
    ra0 = *(const float4*)(Ab);
    ra1 = *(const float4*)(Ab + (size_t)64 * K);
    rb0 = *(const float4*)(Bb);
    rb1 = *(const float4*)(Bb + (size_t)8 * N);
    {
        uint2 u;
        u.x = pack2(ra0.x, ra0.y); u.y = pack2(ra0.z, ra0.w);
        *(uint2*)&As[0][a_row * GSA + a_col] = u;
        u.x = pack2(ra1.x, ra1.y); u.y = pack2(ra1.z, ra1.w);
        *(uint2*)&As[0][(a_row + 64) * GSA + a_col] = u;
        u.x = pack2(rb0.x, rb0.y); u.y = pack2(rb0.z, rb0.w);
        *(uint2*)&Bs[0][b_row * GSB + b_col] = u;
        u.x = pack2(rb1.x, rb1.y); u.y = pack2(rb1.z, rb1.w);
        *(uint2*)&Bs[0][(b_row + 8) * GSB + b_col] = u;
    }
    __syncthreads();

    for (int it = 0; it < NIT; it++) {
        const int cur = it & 1;
        if (it + 1 < NIT) {
            const float* Ap = Ab + (size_t)(it + 1) * 16;
            const float* Bp = Bb + (size_t)(it + 1) * 16 * N;
            ra0 = *(const float4*)(Ap);
            ra1 = *(const float4*)(Ap + (size_t)64 * K);
            rb0 = *(const float4*)(Bp);
            rb1 = *(const float4*)(Bp + (size_t)8 * N);
        }

        const uint32_t asb = as_base + (uint32_t)cur * (128 * GSA * 2);
        const uint32_t bsb = bs_base + (uint32_t)cur * (16 * GSB * 2);

        uint32_t af[2][4];
        ldsm4(af[0], asb + a_off + (uint32_t)wm * GSA * 2);
        ldsm4(af[1], asb + a_off + (uint32_t)(wm + 16) * GSA * 2);
#pragma unroll
        for (int nt16 = 0; nt16 < 4; nt16++) {
            uint32_t bf[4];
            ldsm4t(bf, bsb + b_off + (uint32_t)nt16 * 32);
            mma16816(acc[0][nt16 * 2],     af[0], bf,     acc[0][nt16 * 2]);
            mma16816(acc[0][nt16 * 2 + 1], af[0], bf + 2, acc[0][nt16 * 2 + 1]);
            mma16816(acc[1][nt16 * 2],     af[1], bf,     acc[1][nt16 * 2]);
            mma16816(acc[1][nt16 * 2 + 1], af[1], bf + 2, acc[1][nt16 * 2 + 1]);
        }

        if (it + 1 < NIT) {
            const int nxt = 1 - cur;
            uint2 u;
            u.x = pack2(ra0.x, ra0.y); u.y = pack2(ra0.z, ra0.w);
            *(uint2*)&As[nxt][a_row * GSA + a_col] = u;
            u.x = pack2(ra1.x, ra1.y); u.y = pack2(ra1.z, ra1.w);
            *(uint2*)&As[nxt][(a_row + 64) * GSA + a_col] = u;
            u.x = pack2(rb0.x, rb0.y); u.y = pack2(rb0.z, rb0.w);
            *(uint2*)&Bs[nxt][b_row * GSB + b_col] = u;
            u.x = pack2(rb1.x, rb1.y); u.y = pack2(rb1.z, rb1.w);
            *(uint2*)&Bs[nxt][(b_row + 8) * GSB + b_col] = u;
            __syncthreads();
        }
    }

    // epilogue -> half C
#pragma unroll
    for (int mt = 0; mt < 2; mt++)
#pragma unroll
        for (int nt = 0; nt < 8; nt++) {
            int row0 = m0 + wm + mt * 16 + g;
            int col  = n0 + wn + nt * 8 + 2 * t;
            *(uint32_t*)(C + (size_t)row0 * N + col) =
                pack2(acc[mt][nt][0], acc[mt][nt][1]);
            *(uint32_t*)(C + (size_t)(row0 + 8) * N + col) =
                pack2(acc[mt][nt][2], acc[mt][nt][3]);
        }
}

// ---------------------------------------------------------------------------
// GEMM 2: A half [M,K] @ B f32 [K,N] + bias -> C f32.
// ---------------------------------------------------------------------------
__global__ void __launch_bounds__(256, 2)
gemm_f16a_kernel(const __half* __restrict__ A, const float* __restrict__ B,
                 const float* __restrict__ bias, float* __restrict__ C,
                 int M, int N, int K)
{
    __shared__ __half As[2][128 * GSA];
    __shared__ __half Bs[2][16 * GSB];

    const int tid  = threadIdx.x;
    const int lane = tid & 31;
    const int warp = tid >> 5;
    const int g = lane >> 2;
    const int t = lane & 3;

    const int m0 = blockIdx.y * 128;
    const int n0 = blockIdx.x * 128;
    const int wm = (warp >> 1) * 32;
    const int wn = (warp & 1) * 64;

    const int a_row = tid >> 1;           // 0..127
    const int a_col = (tid & 1) * 8;      // 0 or 8
    const int b_row = tid >> 5;
    const int b_col = (tid & 31) * 4;

    const __half* Ab = A + (size_t)(m0 + a_row) * K + a_col;
    const float*  Bb = B + (size_t)b_row * N + n0 + b_col;

    const uint32_t as_base = sm_u32(&As[0][0]);
    const uint32_t bs_base = sm_u32(&Bs[0][0]);
    const uint32_t a_off = ((uint32_t)((lane & 15) * GSA + (lane >> 4) * 8)) * 2;
    const uint32_t b_off = ((uint32_t)((((lane >> 3) & 1) * 8 + (lane & 7)) * GSB
                                       + wn + (lane >> 4) * 8)) * 2;

    float acc[2][8][4];
#pragma unroll
    for (int i = 0; i < 2; i++)
#pragma unroll
        for (int j = 0; j < 8; j++)
#pragma unroll
            for (int c = 0; c < 4; c++) acc[i][j][c] = 0.0f;

    const int NIT = K >> 4;

    uint4 ra;
    float4 rb0, rb1;
    ra  = *(const uint4*)(Ab);
    rb0 = *(const float4*)(Bb);
    rb1 = *(const float4*)(Bb + (size_t)8 * N);
    {
        *(uint4*)&As[0][a_row * GSA + a_col] = ra;
        uint2 u;
        u.x = pack2(rb0.x, rb0.y); u.y = pack2(rb0.z, rb0.w);
        *(uint2*)&Bs[0][b_row * GSB + b_col] = u;
        u.x = pack2(rb1.x, rb1.y); u.y = pack2(rb1.z, rb1.w);
        *(uint2*)&Bs[0][(b_row + 8) * GSB + b_col] = u;
    }
    __syncthreads();

    for (int it = 0; it < NIT; it++) {
        const int cur = it & 1;
        if (it + 1 < NIT) {
            ra  = *(const uint4*)(Ab + (size_t)(it + 1) * 16);
            const float* Bp = Bb + (size_t)(it + 1) * 16 * N;
            rb0 = *(const float4*)(Bp);
            rb1 = *(const float4*)(Bp + (size_t)8 * N);
        }

        const uint32_t asb = as_base + (uint32_t)cur * (128 * GSA * 2);
        const uint32_t bsb = bs_base + (uint32_t)cur * (16 * GSB * 2);

        uint32_t af[2][4];
        ldsm4(af[0], asb + a_off + (uint32_t)wm * GSA * 2);
        ldsm4(af[1], asb + a_off + (uint32_t)(wm + 16) * GSA * 2);
#pragma unroll
        for (int nt16 = 0; nt16 < 4; nt16++) {
            uint32_t bf[4];
            ldsm4t(bf, bsb + b_off + (uint32_t)nt16 * 32);
            mma16816(acc[0][nt16 * 2],     af[0], bf,     acc[0][nt16 * 2]);
            mma16816(acc[0][nt16 * 2 + 1], af[0], bf + 2, acc[0][nt16 * 2 + 1]);
            mma16816(acc[1][nt16 * 2],     af[1], bf,     acc[1][nt16 * 2]);
            mma16816(acc[1][nt16 * 2 + 1], af[1], bf + 2, acc[1][nt16 * 2 + 1]);
        }

        if (it + 1 < NIT) {
            const int nxt = 1 - cur;
            *(uint4*)&As[nxt][a_row * GSA + a_col] = ra;
            uint2 u;
            u.x = pack2(rb0.x, rb0.y); u.y = pack2(rb0.z, rb0.w);
            *(uint2*)&Bs[nxt][b_row * GSB + b_col] = u;
            u.x = pack2(rb1.x, rb1.y); u.y = pack2(rb1.z, rb1.w);
            *(uint2*)&Bs[nxt][(b_row + 8) * GSB + b_col] = u;
            __syncthreads();
        }
    }

#pragma unroll
    for (int mt = 0; mt < 2; mt++)
#pragma unroll
        for (int nt = 0; nt < 8; nt++) {
            int row0 = m0 + wm + mt * 16 + g;
            int col  = n0 + wn + nt * 8 + 2 * t;
            float b0 = bias[col], b1 = bias[col + 1];
            *(float2*)(C + (size_t)row0 * N + col) =
                make_float2(acc[mt][nt][0] + b0, acc[mt][nt][1] + b1);
            *(float2*)(C + (size_t)(row0 + 8) * N + col) =
                make_float2(acc[mt][nt][2] + b0, acc[mt][nt][3] + b1);
        }
}

// ---------------------------------------------------------------------------
// Flash attention, fp16 mma. CTA = (64-row Q tile, head, batch), 128 thr.
// Q frags register-resident; P converted in-register (no smem round trip).
// ---------------------------------------------------------------------------
#define ASK 72   // Ks/Vs stride (halves): 144B rows -> distinct 16B groups

__global__ void __launch_bounds__(128)
attn_f16_kernel(const __half* __restrict__ qkv, __half* __restrict__ out)
{
    __shared__ __half Ks[64 * ASK];
    __shared__ __half Vs[64 * ASK];

    const int tid  = threadIdx.x;
    const int lane = tid & 31;
    const int warp = tid >> 5;
    const int g = lane >> 2;
    const int t = lane & 3;
    const int wm = warp * 16;

    const int qt = blockIdx.x;
    const int h  = blockIdx.y;
    const int b  = blockIdx.z;

    const __half* base = qkv + (size_t)(b * SEQ) * QKV_N + h * DHEAD;

    const uint32_t ks_base = sm_u32(Ks);
    const uint32_t vs_base = sm_u32(Vs);
    // lane offsets (bytes)
    const uint32_t qa_off = ((uint32_t)((wm + (lane & 15)) * ASK + (lane >> 4) * 8)) * 2;
    const uint32_t kb_off = ((uint32_t)((((lane >> 4) & 1) * 8 + (lane & 7)) * ASK
                                        + ((lane >> 3) & 1) * 8)) * 2;
    const uint32_t vb_off = ((uint32_t)((((lane >> 3) & 1) * 8 + (lane & 7)) * ASK
                                        + (lane >> 4) * 8)) * 2;

    // ---- load Q tile (half) into Ks region ----
    {
        const int row  = tid >> 1;          // 0..63
        const int col8 = (tid & 1) * 8;     // need 64 cols: 8 chunks of 8 per row
#pragma unroll
        for (int i = 0; i < 4; i++) {
            int r = (tid + i * 128) >> 3;
            int c = ((tid + i * 128) & 7) * 8;
            *(uint4*)&Ks[r * ASK + c] =
                *(const uint4*)(base + (size_t)(qt * 64 + r) * QKV_N + c);
        }
        (void)row; (void)col8;
    }
    __syncthreads();

    // ---- Q fragments (register-resident): qf[kg][4], kg = k16 group ----
    uint32_t qf[4][4];
#pragma unroll
    for (int kg = 0; kg < 4; kg++)
        ldsm4(qf[kg], ks_base + qa_off + (uint32_t)kg * 32);

    float O[8][4];
#pragma unroll
    for (int d = 0; d < 8; d++)
#pragma unroll
        for (int c = 0; c < 4; c++) O[d][c] = 0.0f;
    float m0r = -1e30f, m1r = -1e30f, l0r = 0.0f, l1r = 0.0f;

    for (int kt = 0; kt < SEQ / 64; kt++) {
        __syncthreads();   // prior mma reads of Ks/Vs done (and qf build at kt=0)
        // ---- load K/V tiles (half, direct uint4 copies) ----
#pragma unroll
        for (int i = 0; i < 4; i++) {
            int r = (tid + i * 128) >> 3;
            int c = ((tid + i * 128) & 7) * 8;
            const __half* kp = base + DIMM + (size_t)(kt * 64 + r) * QKV_N + c;
            *(uint4*)&Ks[r * ASK + c] = *(const uint4*)kp;
            *(uint4*)&Vs[r * ASK + c] = *(const uint4*)(kp + DIMM);
        }
        __syncthreads();

        // ---- S = Q @ K^T ----
        float S[8][4];
#pragma unroll
        for (int nt = 0; nt < 8; nt++)
#pragma unroll
            for (int c = 0; c < 4; c++) S[nt][c] = 0.0f;

#pragma unroll
        for (int kg = 0; kg < 4; kg++) {
#pragma unroll
            for (int nt16 = 0; nt16 < 4; nt16++) {
                uint32_t bf[4];
                ldsm4(bf, ks_base + kb_off
                          + (uint32_t)nt16 * (16 * ASK * 2) + (uint32_t)kg * 32);
                mma16816(S[nt16 * 2],     qf[kg], bf,     S[nt16 * 2]);
                mma16816(S[nt16 * 2 + 1], qf[kg], bf + 2, S[nt16 * 2 + 1]);
            }
        }

        // ---- online softmax (rows wm+g and wm+g+8) ----
        float mx0 = -1e30f, mx1 = -1e30f;
#pragma unroll
        for (int nt = 0; nt < 8; nt++) {
            S[nt][0] *= SCALE; S[nt][1] *= SCALE;
            S[nt][2] *= SCALE; S[nt][3] *= SCALE;
            mx0 = fmaxf(mx0, fmaxf(S[nt][0], S[nt][1]));
            mx1 = fmaxf(mx1, fmaxf(S[nt][2], S[nt][3]));
        }
        mx0 = fmaxf(mx0, __shfl_xor_sync(0xffffffffu, mx0, 1));
        mx0 = fmaxf(mx0, __shfl_xor_sync(0xffffffffu, mx0, 2));
        mx1 = fmaxf(mx1, __shfl_xor_sync(0xffffffffu, mx1, 1));
        mx1 = fmaxf(mx1, __shfl_xor_sync(0xffffffffu, mx1, 2));

        float mn0 = fmaxf(m0r, mx0);
        float mn1 = fmaxf(m1r, mx1);
        float al0 = __expf(m0r - mn0);
        float al1 = __expf(m1r - mn1);
        m0r = mn0; m1r = mn1;

        float ps0 = 0.0f, ps1 = 0.0f;
#pragma unroll
        for (int nt = 0; nt < 8; nt++) {
            S[nt][0] = __expf(S[nt][0] - mn0);
            S[nt][1] = __expf(S[nt][1] - mn0);
            S[nt][2] = __expf(S[nt][2] - mn1);
            S[nt][3] = __expf(S[nt][3] - mn1);
            ps0 += S[nt][0] + S[nt][1];
            ps1 += S[nt][2] + S[nt][3];
        }
        ps0 += __shfl_xor_sync(0xffffffffu, ps0, 1);
        ps0 += __shfl_xor_sync(0xffffffffu, ps0, 2);
        ps1 += __shfl_xor_sync(0xffffffffu, ps1, 1);
        ps1 += __shfl_xor_sync(0xffffffffu, ps1, 2);
        l0r = l0r * al0 + ps0;
        l1r = l1r * al1 + ps1;

#pragma unroll
        for (int d = 0; d < 8; d++) {
            O[d][0] *= al0; O[d][1] *= al0;
            O[d][2] *= al1; O[d][3] *= al1;
        }

        // ---- P: C-frag(m16n8) pairs == A-frag(m16k16), pure register cvt ----
        uint32_t pa[4][4];
#pragma unroll
        for (int q = 0; q < 4; q++) {
            pa[q][0] = pack2(S[2 * q][0],     S[2 * q][1]);
            pa[q][1] = pack2(S[2 * q][2],     S[2 * q][3]);
            pa[q][2] = pack2(S[2 * q + 1][0], S[2 * q + 1][1]);
            pa[q][3] = pack2(S[2 * q + 1][2], S[2 * q + 1][3]);
        }

        // ---- O += P @ V ----
#pragma unroll
        for (int q = 0; q < 4; q++) {       // j16 groups
#pragma unroll
            for (int dt16 = 0; dt16 < 4; dt16++) {
                uint32_t vf[4];
                ldsm4t(vf, vs_base + vb_off
                           + (uint32_t)q * (16 * ASK * 2) + (uint32_t)dt16 * 32);
                mma16816(O[dt16 * 2],     pa[q], vf,     O[dt16 * 2]);
                mma16816(O[dt16 * 2 + 1], pa[q], vf + 2, O[dt16 * 2 + 1]);
            }
        }
    }

    // ---- epilogue: normalize, write half ----
    float inv0 = 1.0f / l0r;
    float inv1 = 1.0f / l1r;
    __half* ob = out + (size_t)(b * SEQ + qt * 64) * DIMM + h * DHEAD;
#pragma unroll
    for (int dt = 0; dt < 8; dt++) {
        int col = dt * 8 + 2 * t;
        *(uint32_t*)(ob + (size_t)(wm + g) * DIMM + col) =
            pack2(O[dt][0] * inv0, O[dt][1] * inv0);
        *(uint32_t*)(ob + (size_t)(wm + g + 8) * DIMM + col) =
            pack2(O[dt][2] * inv1, O[dt][3] * inv1);
    }
}

// ---------------------------------------------------------------------------

extern "C" void kernel_launch(void* const* d_in, const int* in_sizes, int n_in,
                              void* d_out, int out_size)
{
    const float* x     = (const float*)d_in[0];   // [2,2048,1024]
    const float* W_qkv = (const float*)d_in[1];   // [1024,3072]
    const float* W_out = (const float*)d_in[2];   // [1024,1024]
    const float* b_out = (const float*)d_in[3];   // [1024]
    float* out = (float*)d_out;                   // [2,2048,1024]

    __half* qkv = nullptr;
    __half* att = nullptr;
    cudaGetSymbolAddress((void**)&qkv, g_qkv);
    cudaGetSymbolAddress((void**)&att, g_att);

    // 1) QKV projection -> half scratch
    {
        dim3 grid(QKV_N / 128, ROWS / 128);
        gemm_f32a_kernel<<<grid, 256>>>(x, W_qkv, qkv, ROWS, QKV_N, DIMM);
    }

    // 2) attention (half in, half out)
    {
        dim3 grid(SEQ / 64, HEADS, BATCH);
        attn_f16_kernel<<<grid, 128>>>(qkv, att);
    }

    // 3) output projection + bias -> f32
    {
        dim3 grid(DIMM / 128, ROWS / 128);
        gemm_f16a_kernel<<<grid, 256>>>(att, W_out, b_out, out, ROWS, DIMM, DIMM);
    }
}